// round 3
// baseline (speedup 1.0000x reference)
#include <cuda_runtime.h>
#include <math_constants.h>

// Problem: out = softmax(h_flat @ M^T) @ M
// h: [8,16,64,512] -> [8192, 512] fp32 ; M: [20000, 512] fp32
// Flash-attention style online softmax, fp32 SIMT baseline.

#define BM 32          // rows per CTA
#define BK 64          // keys per tile
#define RDIM 512
#define RP 516         // padded row stride (floats) -> odd float4 stride, kills conflicts
#define PSTRIDE 65     // probs tile row stride
#define NTHREADS 256
#define KDIM 20000
#define NROWS 8192
#define NTILES ((KDIM + BK - 1) / BK)   // 313

// smem: sH[BM*RP] + sMt[BK*RP] + sP[BM*PSTRIDE] + mrow/lrow/srow[BM each]
#define SMEM_FLOATS (BM*RP + BK*RP + BM*PSTRIDE + 3*BM)
#define SMEM_BYTES (SMEM_FLOATS * 4)

__global__ __launch_bounds__(NTHREADS, 1)
void mc2_attn_kernel(const float* __restrict__ h,
                     const float* __restrict__ M,
                     float* __restrict__ out) {
    extern __shared__ float sm[];
    float* sH   = sm;
    float* sMt  = sH + BM * RP;
    float* sP   = sMt + BK * RP;
    float* mrow = sP + BM * PSTRIDE;
    float* lrow = mrow + BM;
    float* srow = lrow + BM;

    const int tid  = threadIdx.x;
    const int lane = tid & 31;
    const int warp = tid >> 5;          // 0..7
    const int row0 = blockIdx.x * BM;

    // ---- load h block [32 x 512] into smem (padded rows) ----
    {
        const float4* hg = (const float4*)(h + (size_t)row0 * RDIM);
        #pragma unroll
        for (int i = 0; i < (BM * RDIM / 4) / NTHREADS; i++) {   // 16
            int idx = tid + i * NTHREADS;
            int r   = idx >> 7;        // /128 float4 per row
            int c4  = idx & 127;
            float4 v = hg[r * 128 + c4];
            *(float4*)(sH + r * RP + c4 * 4) = v;
        }
    }
    if (tid < BM) { mrow[tid] = -CUDART_INF_F; lrow[tid] = 0.f; }

    // layout A (S-GEMM): 16 rowgroups x 16 keygroups; keys strided by 16
    const int rg = tid >> 4;   // 0..15 -> rows {2rg, 2rg+1}
    const int kg = tid & 15;   // 0..15 -> keys {kg+16j, j=0..3}
    // layout B (O-GEMM): 4 rowgroups x 64 colgroups
    const int rb = tid >> 6;   // 0..3  -> rows 8rb..8rb+7
    const int cb = tid & 63;   // 0..63 -> cols 8cb..8cb+7

    float o[8][8];
    #pragma unroll
    for (int i = 0; i < 8; i++)
        #pragma unroll
        for (int j = 0; j < 8; j++) o[i][j] = 0.f;

    for (int kt = 0; kt < NTILES; kt++) {
        const int kbase = kt * BK;
        __syncthreads();   // protect sMt from previous iteration's readers

        // ---- load M tile [64 x 512] ----
        {
            const float4* mg = (const float4*)(M + (size_t)kbase * RDIM);
            #pragma unroll
            for (int i = 0; i < (BK * RDIM / 4) / NTHREADS; i++) {  // 32
                int idx = tid + i * NTHREADS;
                int r   = idx >> 7;
                int c4  = idx & 127;
                if (kbase + r < KDIM) {
                    float4 v = mg[r * 128 + c4];
                    *(float4*)(sMt + r * RP + c4 * 4) = v;
                }
            }
        }
        __syncthreads();

        // ---- S = h_blk @ Mt^T  (logits) ----
        float acc[2][4];
        #pragma unroll
        for (int i = 0; i < 2; i++)
            #pragma unroll
            for (int j = 0; j < 4; j++) acc[i][j] = 0.f;

        const float* hr0 = sH + (2 * rg)     * RP;
        const float* hr1 = sH + (2 * rg + 1) * RP;

        #pragma unroll 4
        for (int rc = 0; rc < RDIM; rc += 4) {
            float4 h0 = *(const float4*)(hr0 + rc);
            float4 h1 = *(const float4*)(hr1 + rc);
            #pragma unroll
            for (int j = 0; j < 4; j++) {
                float4 mv = *(const float4*)(sMt + (kg + 16 * j) * RP + rc);
                acc[0][j] += h0.x * mv.x + h0.y * mv.y + h0.z * mv.z + h0.w * mv.w;
                acc[1][j] += h1.x * mv.x + h1.y * mv.y + h1.z * mv.z + h1.w * mv.w;
            }
        }

        // write logits to sP with OOB masking
        #pragma unroll
        for (int i = 0; i < 2; i++)
            #pragma unroll
            for (int j = 0; j < 4; j++) {
                int key = kg + 16 * j;
                float v = (kbase + key < KDIM) ? acc[i][j] : -CUDART_INF_F;
                sP[(2 * rg + i) * PSTRIDE + key] = v;
            }
        __syncthreads();

        // ---- online softmax update: warp w handles rows {w, w+8, w+16, w+24} ----
        // Each lane covers 2 keys (lane, lane+32) of the 64-key tile.
        #pragma unroll
        for (int rr = 0; rr < 4; rr++) {
            int r = warp + 8 * rr;
            float* pr = sP + r * PSTRIDE;
            float v0 = pr[lane];
            float v1 = pr[lane + 32];
            float mt = fmaxf(v0, v1);
            #pragma unroll
            for (int off = 16; off > 0; off >>= 1)
                mt = fmaxf(mt, __shfl_xor_sync(0xFFFFFFFFu, mt, off));
            float mo = mrow[r];
            mt = fmaxf(mt, mo);
            float e0 = __expf(v0 - mt);
            float e1 = __expf(v1 - mt);
            pr[lane]      = e0;
            pr[lane + 32] = e1;
            float s = e0 + e1;
            #pragma unroll
            for (int off = 16; off > 0; off >>= 1)
                s += __shfl_xor_sync(0xFFFFFFFFu, s, off);
            if (lane == 0) {
                float corr = __expf(mo - mt);
                lrow[r] = lrow[r] * corr + s;
                mrow[r] = mt;
                srow[r] = corr;
            }
        }
        __syncthreads();

        // ---- O = O*corr + P @ Mt ----
        #pragma unroll
        for (int i = 0; i < 8; i++) {
            float s = srow[8 * rb + i];
            #pragma unroll
            for (int j = 0; j < 8; j++) o[i][j] *= s;
        }
        for (int k = 0; k < BK; k++) {
            float4 m0 = *(const float4*)(sMt + k * RP + 8 * cb);
            float4 m1 = *(const float4*)(sMt + k * RP + 8 * cb + 4);
            #pragma unroll
            for (int i = 0; i < 8; i++) {
                float p = sP[(8 * rb + i) * PSTRIDE + k];
                o[i][0] += p * m0.x;
                o[i][1] += p * m0.y;
                o[i][2] += p * m0.z;
                o[i][3] += p * m0.w;
                o[i][4] += p * m1.x;
                o[i][5] += p * m1.y;
                o[i][6] += p * m1.z;
                o[i][7] += p * m1.w;
            }
        }
    }

    // ---- epilogue: divide by softmax denominator, write out ----
    #pragma unroll
    for (int i = 0; i < 8; i++) {
        float inv = 1.f / lrow[8 * rb + i];
        size_t base = ((size_t)(row0 + 8 * rb + i)) * RDIM + 8 * cb;
        float4 v0, v1;
        v0.x = o[i][0] * inv; v0.y = o[i][1] * inv;
        v0.z = o[i][2] * inv; v0.w = o[i][3] * inv;
        v1.x = o[i][4] * inv; v1.y = o[i][5] * inv;
        v1.z = o[i][6] * inv; v1.w = o[i][7] * inv;
        *(float4*)(out + base)     = v0;
        *(float4*)(out + base + 4) = v1;
    }
}

extern "C" void kernel_launch(void* const* d_in, const int* in_sizes, int n_in,
                              void* d_out, int out_size) {
    const float* h = (const float*)d_in[0];   // [8192, 512]
    const float* M = (const float*)d_in[1];   // [20000, 512]
    float* out = (float*)d_out;               // [8192, 512]

    cudaFuncSetAttribute(mc2_attn_kernel,
                         cudaFuncAttributeMaxDynamicSharedMemorySize, SMEM_BYTES);
    mc2_attn_kernel<<<NROWS / BM, NTHREADS, SMEM_BYTES>>>(h, M, out);
}